// round 13
// baseline (speedup 1.0000x reference)
#include <cuda_runtime.h>
#include <cuda_fp16.h>
#include <cstdint>
#include <math.h>

#define B_  4
#define S_  2048
#define H_  1024
#define NH_ 16
#define HD_ 64
#define L2E 1.44269504088896f

// f16 scratch.
__device__ __half g_hs[8192 * 1024];          // hidden, f16 [8192][1024]
__device__ __half g_wt[3][1024 * 1024];       // W^T f16 [n][k] for Q,K,V
__device__ __half g_qh[64 * 2048 * 64];       // Q f16 [bh][s][d], scaled log2e/8
__device__ __half g_kh[64 * 2048 * 64];       // K f16 [bh][s][perm d] (row-permuted)
__device__ __half g_vt[64 * 64 * 2048];       // V^T f16 [bh][d][perm s] (chunk-permuted)

__device__ __forceinline__ void mma16(float* c, const unsigned* a, const unsigned* b) {
    asm volatile(
        "mma.sync.aligned.m16n8k16.row.col.f32.f16.f16.f32 "
        "{%0,%1,%2,%3}, {%4,%5,%6,%7}, {%8,%9}, {%0,%1,%2,%3};\n"
        : "+f"(c[0]), "+f"(c[1]), "+f"(c[2]), "+f"(c[3])
        : "r"(a[0]), "r"(a[1]), "r"(a[2]), "r"(a[3]), "r"(b[0]), "r"(b[1]));
}

__device__ __forceinline__ void cpa16(void* dst, const void* src) {
    unsigned d = (unsigned)__cvta_generic_to_shared(dst);
    asm volatile("cp.async.cg.shared.global [%0], [%1], 16;\n" :: "r"(d), "l"(src));
}
#define CP_COMMIT asm volatile("cp.async.commit_group;\n" ::: "memory")
#define CP_WAIT1  asm volatile("cp.async.wait_group 1;\n" ::: "memory")

__device__ __forceinline__ unsigned h2u(float x, float y) {
    __half2 h = __floats2half2_rn(x, y);
    return *reinterpret_cast<unsigned*>(&h);
}

// Fragment-gather permutation of a 32-word (64-half) group:
// old word w -> new word (w&7)*4 + (w>>3). Thread (g,t) then reads its 8
// B-fragment words as two contiguous uint4s at new words 4t and 4t+16.
__device__ __forceinline__ int wperm(int w) { return (w & 7) * 4 + (w >> 3); }

// ---------------------------------------------------------------------------
// Prep 1: hidden f32 -> f16.
// ---------------------------------------------------------------------------
__global__ __launch_bounds__(256) void cvt_hs(const float* __restrict__ hs) {
    int i = blockIdx.x * 256 + threadIdx.x;
    float4 v = ((const float4*)hs)[i];
    ((uint2*)g_hs)[i] = make_uint2(h2u(v.x, v.y), h2u(v.z, v.w));
}

// ---------------------------------------------------------------------------
// Prep 2: W -> W^T f16 (tiled transpose). grid (32,32,3), block (32,8).
// ---------------------------------------------------------------------------
__global__ __launch_bounds__(256) void cvt_wt(
    const float* __restrict__ Wq, const float* __restrict__ Wk,
    const float* __restrict__ Wv)
{
    __shared__ float t[32][33];
    const float* W = blockIdx.z == 0 ? Wq : (blockIdx.z == 1 ? Wk : Wv);
    __half* wt = g_wt[blockIdx.z];
    int tx = threadIdx.x, ty = threadIdx.y;
    int n0 = blockIdx.x * 32, k0 = blockIdx.y * 32;
    #pragma unroll
    for (int j = 0; j < 4; j++)
        t[ty + 8 * j][tx] = W[(size_t)(k0 + ty + 8 * j) * H_ + n0 + tx];
    __syncthreads();
    #pragma unroll
    for (int j = 0; j < 4; j++)
        wt[(size_t)(n0 + ty + 8 * j) * H_ + k0 + tx] =
            __float2half(t[tx][ty + 8 * j]);
}

// ---------------------------------------------------------------------------
// Kernel 1: fused QKV projection, f16 mma m16n8k16, cp.async double-buffered.
//   BM=128, BN=128, BK=32. 8 warps (4m x 2n), warp tile 32x64.
// ---------------------------------------------------------------------------
#define TS 20   // tile row stride in 32-bit words (16 data + 4 pad)
#define QKV_SMEM ((2 * 128 * TS + 2 * 128 * TS) * 4)

__global__ __launch_bounds__(256, 2) void qkv_proj(
    const float* __restrict__ bq, const float* __restrict__ bk,
    const float* __restrict__ bv,
    const float* __restrict__ qe, const float* __restrict__ ke,
    const float* __restrict__ ve,
    const int* __restrict__ indexp)
{
    extern __shared__ unsigned qsm[];
    unsigned* AsW = qsm;                  // [2][128][TS]
    unsigned* BsW = qsm + 2 * 128 * TS;   // [2][128][TS]
#define AT(bf,r,w) AsW[(bf)*128*TS + (r)*TS + (w)]
#define BT(bf,r,w) BsW[(bf)*128*TS + (r)*TS + (w)]

    const int tid  = threadIdx.x;
    const int lane = tid & 31;
    const int wid  = tid >> 5;
    const int g    = lane >> 2;
    const int t    = lane & 3;
    const int wm   = wid & 3;
    const int wn   = wid >> 2;

    const int nb  = blockIdx.x;   // 0..23, 8 per matrix
    const int mb  = blockIdx.y;   // 0..63
    const int sel = nb >> 3;      // 0=Q, 1=K, 2=V

    const __half* wt  = g_wt[sel];
    const float* bias = sel == 0 ? bq : (sel == 1 ? bk : bv);
    const float* emb  = (sel == 0 ? qe : (sel == 1 ? ke : ve)) + indexp[0] * H_;
    const float sc    = sel == 0 ? (0.125f * L2E) : 1.0f;

    const int colm = (nb & 7) * 128;
    const int row0 = mb * 128;

    float acc[2][8][4] = {};

    auto stage = [&](int kt, int bf) {
        #pragma unroll
        for (int i = 0; i < 2; i++) {
            int idx = tid + i * 256;
            int r = idx >> 2, ch = idx & 3;
            cpa16(&AT(bf, r, ch * 4), &g_hs[(size_t)(row0 + r) * H_ + kt + ch * 8]);
            cpa16(&BT(bf, r, ch * 4), &wt[(size_t)(colm + r) * H_ + kt + ch * 8]);
        }
    };

    stage(0, 0);
    CP_COMMIT;

    for (int it = 0; it < H_ / 32; it++) {
        const int bf = it & 1;
        if (it + 1 < H_ / 32) stage((it + 1) * 32, bf ^ 1);
        CP_COMMIT;
        CP_WAIT1;
        __syncthreads();

        #pragma unroll
        for (int kk = 0; kk < 2; kk++) {
            unsigned a[2][4];
            #pragma unroll
            for (int mt = 0; mt < 2; mt++) {
                int r = wm * 32 + mt * 16;
                a[mt][0] = AT(bf, r + g,     kk * 8 + t);
                a[mt][1] = AT(bf, r + g + 8, kk * 8 + t);
                a[mt][2] = AT(bf, r + g,     kk * 8 + t + 4);
                a[mt][3] = AT(bf, r + g + 8, kk * 8 + t + 4);
            }
            #pragma unroll
            for (int nt = 0; nt < 8; nt++) {
                int c = wn * 64 + nt * 8 + g;
                unsigned bb[2] = { BT(bf, c, kk * 8 + t),
                                   BT(bf, c, kk * 8 + t + 4) };
                mma16(acc[0][nt], a[0], bb);
                mma16(acc[1][nt], a[1], bb);
            }
        }
        __syncthreads();
    }

    // Epilogue: +bias+emb, (Q: *log2e/8), f16, scatter.
    // K rows and V^T s-chunks are written in fragment-gather permuted order.
    #pragma unroll
    for (int nt = 0; nt < 8; nt++) {
        const int cm   = colm + wn * 64 + nt * 8 + 2 * t;
        const float b0 = bias[cm]     + emb[cm];
        const float b1 = bias[cm + 1] + emb[cm + 1];
        const int head = cm >> 6;
        const int d    = cm & 63;
        #pragma unroll
        for (int mt = 0; mt < 2; mt++) {
            int row = row0 + wm * 32 + mt * 16 + g;
            int bt  = row >> 11;
            int s   = row & 2047;
            int bh  = bt * NH_ + head;
            float x0 = (acc[mt][nt][0] + b0) * sc;
            float x1 = (acc[mt][nt][1] + b1) * sc;
            float x2 = (acc[mt][nt][2] + b0) * sc;
            float x3 = (acc[mt][nt][3] + b1) * sc;
            if (sel == 0) {
                __half* dst = g_qh + ((size_t)bh * S_ + s) * HD_ + d;
                *(unsigned*)dst             = h2u(x0, x1);
                *(unsigned*)(dst + 8 * HD_) = h2u(x2, x3);
            } else if (sel == 1) {
                const int pw = wperm(d >> 1);   // d is even
                unsigned* dw = (unsigned*)(g_kh + ((size_t)bh * S_ + s) * HD_);
                dw[pw]                 = h2u(x0, x1);
                dw[pw + 8 * HD_ / 2]   = h2u(x2, x3);   // row s+8
            } else {
                __half* dst = g_vt + (size_t)bh * HD_ * S_;
                const int p0 = (s & ~63) | (wperm((s >> 1) & 31) * 2) | (s & 1);
                const int s8 = s + 8;
                const int p8 = (s8 & ~63) | (wperm((s8 >> 1) & 31) * 2) | (s8 & 1);
                dst[(size_t)d       * S_ + p0] = __float2half(x0);
                dst[(size_t)(d + 1) * S_ + p0] = __float2half(x1);
                dst[(size_t)d       * S_ + p8] = __float2half(x2);
                dst[(size_t)(d + 1) * S_ + p8] = __float2half(x3);
            }
        }
    }
#undef AT
#undef BT
}

// ---------------------------------------------------------------------------
// Kernel 2: flash attention. 8 warps x 16 q-rows, 64-key tiles.
//   3-stage cp.async ring, ONE __syncthreads per tile. exp2-domain softmax.
//   Fragment loads are uint4 (LDS.128) thanks to the permuted K/V^T layout:
//   thread (g,t) reads its 4 dc/kc B-frag word pairs as rows[4t..4t+3] and
//   rows[4t+16..4t+19]. FS=48 (stride 16 mod 32) -> octets cover disjoint
//   bank halves -> conflict-free LDS.128.
// ---------------------------------------------------------------------------
#define FS 48
#define FL_SMEM ((3 * 2 * 64 * FS + 3 * 64) * 4)

__global__ __launch_bounds__(256, 2) void flash_attn(
    const float* __restrict__ mask, float* __restrict__ out)
{
    extern __shared__ unsigned fsm[];
    unsigned* KsW = fsm;                  // [3][64 keys][FS]
    unsigned* VtW = fsm + 3 * 64 * FS;    // [3][64 dims][FS]
    float*    Ms  = (float*)(fsm + 6 * 64 * FS);  // [3][64]
#define KT(bf,r,w) KsW[(bf)*64*FS + (r)*FS + (w)]
#define VT(bf,r,w) VtW[(bf)*64*FS + (r)*FS + (w)]

    const int tid  = threadIdx.x;
    const int lane = tid & 31;
    const int wid  = tid >> 5;
    const int g    = lane >> 2;
    const int t    = lane & 3;

    const int bh = blockIdx.y;
    const int b  = bh >> 4, h = bh & 15;
    const __half* Qp  = g_qh + (size_t)bh * S_ * HD_;
    const __half* Kp  = g_kh + (size_t)bh * S_ * HD_;
    const __half* Vtp = g_vt + (size_t)bh * HD_ * S_;
    const float* maskp = mask + b * S_;
    const int q0 = blockIdx.x * 128 + wid * 16;

    auto stage = [&](int kt, int bf) {
        #pragma unroll
        for (int i = 0; i < 2; i++) {
            int idx = tid + i * 256;
            int r = idx >> 3, ch = idx & 7;
            cpa16(&KT(bf, r, ch * 4), &Kp[(size_t)(kt + r) * HD_ + ch * 8]);
            cpa16(&VT(bf, r, ch * 4), &Vtp[(size_t)r * S_ + kt + ch * 8]);
        }
        if (tid < 16) cpa16(&Ms[bf * 64 + tid * 4], &maskp[kt + tid * 4]);
    };

    // Q A-fragments (f16 pairs, pre-scaled by log2e/8), resident.
    unsigned qa[4][4];
    {
        const __half* q0p = Qp + (size_t)(q0 + g) * HD_;
        const __half* q8p = q0p + 8 * HD_;
        #pragma unroll
        for (int dc = 0; dc < 4; dc++) {
            qa[dc][0] = *(const unsigned*)(q0p + dc * 16 + 2 * t);
            qa[dc][1] = *(const unsigned*)(q8p + dc * 16 + 2 * t);
            qa[dc][2] = *(const unsigned*)(q0p + dc * 16 + 2 * t + 8);
            qa[dc][3] = *(const unsigned*)(q8p + dc * 16 + 2 * t + 8);
        }
    }

    float o[8][4] = {};
    float mr0 = -1e30f, mr1 = -1e30f, lr0 = 0.f, lr1 = 0.f;

    // Ring prologue: stages 0 and 1 in flight.
    stage(0, 0);
    CP_COMMIT;
    stage(64, 1);
    CP_COMMIT;

    int bf = 0, bs = 2;   // compute buffer, next stage buffer
    for (int it = 0; it < S_ / 64; it++) {
        CP_WAIT1;          // group 'it' complete (one group may stay in flight)
        __syncthreads();   // single barrier per tile

        // S = Q @ K^T  (log2 domain). Two LDS.128 per key row.
        float s[8][4] = {};
        #pragma unroll
        for (int nt = 0; nt < 8; nt++) {
            unsigned lo[4], hi[4];
            *(uint4*)lo = *(const uint4*)&KT(bf, nt * 8 + g, 4 * t);
            *(uint4*)hi = *(const uint4*)&KT(bf, nt * 8 + g, 4 * t + 16);
            #pragma unroll
            for (int dc = 0; dc < 4; dc++) {
                unsigned bb[2] = { lo[dc], hi[dc] };
                mma16(s[nt], qa[dc], bb);
            }
        }

        // mask (scaled into log2 domain) + row max
        float r0 = -1e30f, r1 = -1e30f;
        #pragma unroll
        for (int nt = 0; nt < 8; nt++) {
            float m0 = Ms[bf * 64 + nt * 8 + 2 * t]     * L2E;
            float m1 = Ms[bf * 64 + nt * 8 + 2 * t + 1] * L2E;
            s[nt][0] += m0; s[nt][1] += m1; s[nt][2] += m0; s[nt][3] += m1;
            r0 = fmaxf(r0, fmaxf(s[nt][0], s[nt][1]));
            r1 = fmaxf(r1, fmaxf(s[nt][2], s[nt][3]));
        }
        r0 = fmaxf(r0, __shfl_xor_sync(0xffffffffu, r0, 1));
        r0 = fmaxf(r0, __shfl_xor_sync(0xffffffffu, r0, 2));
        r1 = fmaxf(r1, __shfl_xor_sync(0xffffffffu, r1, 1));
        r1 = fmaxf(r1, __shfl_xor_sync(0xffffffffu, r1, 2));

        float mn0 = fmaxf(mr0, r0), mn1 = fmaxf(mr1, r1);
        float al0 = exp2f(mr0 - mn0), al1 = exp2f(mr1 - mn1);
        mr0 = mn0; mr1 = mn1;

        // P = exp2(S - m), row sums
        float ps0 = 0.f, ps1 = 0.f;
        #pragma unroll
        for (int nt = 0; nt < 8; nt++) {
            s[nt][0] = exp2f(s[nt][0] - mn0);
            s[nt][1] = exp2f(s[nt][1] - mn0);
            s[nt][2] = exp2f(s[nt][2] - mn1);
            s[nt][3] = exp2f(s[nt][3] - mn1);
            ps0 += s[nt][0] + s[nt][1];
            ps1 += s[nt][2] + s[nt][3];
        }
        ps0 += __shfl_xor_sync(0xffffffffu, ps0, 1);
        ps0 += __shfl_xor_sync(0xffffffffu, ps0, 2);
        ps1 += __shfl_xor_sync(0xffffffffu, ps1, 1);
        ps1 += __shfl_xor_sync(0xffffffffu, ps1, 2);
        lr0 = lr0 * al0 + ps0;
        lr1 = lr1 * al1 + ps1;

        // Pack all P A-fragments first, then O = O*alpha + P @ V with
        // two LDS.128 per dim row.
        unsigned a[4][4];
        #pragma unroll
        for (int kc = 0; kc < 4; kc++) {
            a[kc][0] = h2u(s[2*kc][0],   s[2*kc][1]);
            a[kc][1] = h2u(s[2*kc][2],   s[2*kc][3]);
            a[kc][2] = h2u(s[2*kc+1][0], s[2*kc+1][1]);
            a[kc][3] = h2u(s[2*kc+1][2], s[2*kc+1][3]);
        }
        #pragma unroll
        for (int dt = 0; dt < 8; dt++) {
            o[dt][0] *= al0; o[dt][1] *= al0;
            o[dt][2] *= al1; o[dt][3] *= al1;
        }
        #pragma unroll
        for (int dt = 0; dt < 8; dt++) {
            unsigned lo[4], hi[4];
            *(uint4*)lo = *(const uint4*)&VT(bf, dt * 8 + g, 4 * t);
            *(uint4*)hi = *(const uint4*)&VT(bf, dt * 8 + g, 4 * t + 16);
            #pragma unroll
            for (int kc = 0; kc < 4; kc++) {
                unsigned bb[2] = { lo[kc], hi[kc] };
                mma16(o[dt], a[kc], bb);
            }
        }

        // Stage tile it+2 into ring slot bs.
        if (it + 2 < S_ / 64) stage((it + 2) * 64, bs);
        CP_COMMIT;

        bf = bf == 2 ? 0 : bf + 1;
        bs = bs == 2 ? 0 : bs + 1;
    }

    // Normalize and write ctx [B, S, NH*HD] f32.
    const float i0 = 1.0f / lr0, i1 = 1.0f / lr1;
    #pragma unroll
    for (int dt = 0; dt < 8; dt++) {
        size_t base = (size_t)(b * S_ + q0 + g) * H_ + h * HD_ + dt * 8 + 2 * t;
        *(float2*)&out[base] = make_float2(o[dt][0] * i0, o[dt][1] * i0);
        *(float2*)&out[base + 8 * (size_t)H_] =
            make_float2(o[dt][2] * i1, o[dt][3] * i1);
    }
#undef KT
#undef VT
}

// ---------------------------------------------------------------------------
extern "C" void kernel_launch(void* const* d_in, const int* in_sizes, int n_in,
                              void* d_out, int out_size)
{
    const float* hs   = (const float*)d_in[0];
    const float* mask = (const float*)d_in[1];
    const float* Wq   = (const float*)d_in[2];
    const float* bq   = (const float*)d_in[3];
    const float* Wk   = (const float*)d_in[4];
    const float* bk   = (const float*)d_in[5];
    const float* Wv   = (const float*)d_in[6];
    const float* bv   = (const float*)d_in[7];
    const float* qe   = (const float*)d_in[8];
    const float* ke   = (const float*)d_in[9];
    const float* ve   = (const float*)d_in[10];
    const int*   idx  = (const int*)d_in[11];

    cudaFuncSetAttribute(qkv_proj, cudaFuncAttributeMaxDynamicSharedMemorySize,
                         QKV_SMEM);
    cudaFuncSetAttribute(flash_attn, cudaFuncAttributeMaxDynamicSharedMemorySize,
                         FL_SMEM);

    cvt_hs<<<8192, 256>>>(hs);
    cvt_wt<<<dim3(32, 32, 3), dim3(32, 8)>>>(Wq, Wk, Wv);

    dim3 g1(24, 64);
    qkv_proj<<<g1, 256, QKV_SMEM>>>(bq, bk, bv, qe, ke, ve, idx);

    dim3 g2(S_ / 128, B_ * NH_);
    flash_attn<<<g2, 256, FL_SMEM>>>(mask, (float*)d_out);
}

// round 16
// speedup vs baseline: 1.1106x; 1.1106x over previous
#include <cuda_runtime.h>
#include <cuda_fp16.h>
#include <cstdint>
#include <math.h>

#define B_  4
#define S_  2048
#define H_  1024
#define NH_ 16
#define HD_ 64
#define L2E 1.44269504088896f

// f16 scratch.
__device__ __half g_hs[8192 * 1024];          // hidden, f16 [8192][1024]
__device__ __half g_wt[3][1024 * 1024];       // W^T f16 [n][k] for Q,K,V
__device__ __half g_qh[64 * 2048 * 64];       // Q f16 [bh][s][d], scaled log2e/8
__device__ __half g_kh[64 * 2048 * 64];       // K f16 [bh][s][d]
__device__ __half g_vt[64 * 64 * 2048];       // V^T f16 [bh][d][s]
__device__ float  g_mask[B_ * S_];            // mask * log2e

__device__ __forceinline__ void mma16(float* c, const unsigned* a, const unsigned* b) {
    asm volatile(
        "mma.sync.aligned.m16n8k16.row.col.f32.f16.f16.f32 "
        "{%0,%1,%2,%3}, {%4,%5,%6,%7}, {%8,%9}, {%0,%1,%2,%3};\n"
        : "+f"(c[0]), "+f"(c[1]), "+f"(c[2]), "+f"(c[3])
        : "r"(a[0]), "r"(a[1]), "r"(a[2]), "r"(a[3]), "r"(b[0]), "r"(b[1]));
}

__device__ __forceinline__ void cpa16(void* dst, const void* src) {
    unsigned d = (unsigned)__cvta_generic_to_shared(dst);
    asm volatile("cp.async.cg.shared.global [%0], [%1], 16;\n" :: "r"(d), "l"(src));
}
#define CP_COMMIT asm volatile("cp.async.commit_group;\n" ::: "memory")
#define CP_WAIT1  asm volatile("cp.async.wait_group 1;\n" ::: "memory")

__device__ __forceinline__ unsigned h2u(float x, float y) {
    __half2 h = __floats2half2_rn(x, y);
    return *reinterpret_cast<unsigned*>(&h);
}

// exp2 of two f32 values, result packed f16x2 {lo=2^x, hi=2^y}.
__device__ __forceinline__ unsigned ex2h2(float x, float y) {
    unsigned h;
    asm("{\n\t.reg .b32 t;\n\t"
        "cvt.rn.f16x2.f32 t, %2, %1;\n\t"   // hi=y, lo=x
        "ex2.approx.f16x2 %0, t;\n\t}"
        : "=r"(h) : "f"(x), "f"(y));
    return h;
}

// ---------------------------------------------------------------------------
// Prep 1: hidden f32 -> f16.
// ---------------------------------------------------------------------------
__global__ __launch_bounds__(256) void cvt_hs(const float* __restrict__ hs) {
    int i = blockIdx.x * 256 + threadIdx.x;
    float4 v = ((const float4*)hs)[i];
    ((uint2*)g_hs)[i] = make_uint2(h2u(v.x, v.y), h2u(v.z, v.w));
}

// ---------------------------------------------------------------------------
// Prep 1b: mask * log2e.
// ---------------------------------------------------------------------------
__global__ __launch_bounds__(256) void cvt_mask(const float* __restrict__ m) {
    int i = blockIdx.x * 256 + threadIdx.x;
    g_mask[i] = m[i] * L2E;
}

// ---------------------------------------------------------------------------
// Prep 2: W -> W^T f16 (tiled transpose). grid (32,32,3), block (32,8).
// ---------------------------------------------------------------------------
__global__ __launch_bounds__(256) void cvt_wt(
    const float* __restrict__ Wq, const float* __restrict__ Wk,
    const float* __restrict__ Wv)
{
    __shared__ float t[32][33];
    const float* W = blockIdx.z == 0 ? Wq : (blockIdx.z == 1 ? Wk : Wv);
    __half* wt = g_wt[blockIdx.z];
    int tx = threadIdx.x, ty = threadIdx.y;
    int n0 = blockIdx.x * 32, k0 = blockIdx.y * 32;
    #pragma unroll
    for (int j = 0; j < 4; j++)
        t[ty + 8 * j][tx] = W[(size_t)(k0 + ty + 8 * j) * H_ + n0 + tx];
    __syncthreads();
    #pragma unroll
    for (int j = 0; j < 4; j++)
        wt[(size_t)(n0 + ty + 8 * j) * H_ + k0 + tx] =
            __float2half(t[tx][ty + 8 * j]);
}

// ---------------------------------------------------------------------------
// Kernel 1: fused QKV projection (round-12 proven), f16 mma m16n8k16,
//   cp.async double-buffered. BM=128, BN=128, BK=32. 8 warps (4m x 2n).
// ---------------------------------------------------------------------------
#define TS 20   // tile row stride in 32-bit words (16 data + 4 pad)
#define QKV_SMEM ((2 * 128 * TS + 2 * 128 * TS) * 4)

__global__ __launch_bounds__(256, 2) void qkv_proj(
    const float* __restrict__ bq, const float* __restrict__ bk,
    const float* __restrict__ bv,
    const float* __restrict__ qe, const float* __restrict__ ke,
    const float* __restrict__ ve,
    const int* __restrict__ indexp)
{
    extern __shared__ unsigned qsm[];
    unsigned* AsW = qsm;                  // [2][128][TS]
    unsigned* BsW = qsm + 2 * 128 * TS;   // [2][128][TS]
#define AT(bf,r,w) AsW[(bf)*128*TS + (r)*TS + (w)]
#define BT(bf,r,w) BsW[(bf)*128*TS + (r)*TS + (w)]

    const int tid  = threadIdx.x;
    const int lane = tid & 31;
    const int wid  = tid >> 5;
    const int g    = lane >> 2;
    const int t    = lane & 3;
    const int wm   = wid & 3;
    const int wn   = wid >> 2;

    const int nb  = blockIdx.x;   // 0..23, 8 per matrix
    const int mb  = blockIdx.y;   // 0..63
    const int sel = nb >> 3;      // 0=Q, 1=K, 2=V

    const __half* wt  = g_wt[sel];
    const float* bias = sel == 0 ? bq : (sel == 1 ? bk : bv);
    const float* emb  = (sel == 0 ? qe : (sel == 1 ? ke : ve)) + indexp[0] * H_;
    const float sc    = sel == 0 ? (0.125f * L2E) : 1.0f;

    const int colm = (nb & 7) * 128;
    const int row0 = mb * 128;

    float acc[2][8][4] = {};

    auto stage = [&](int kt, int bf) {
        #pragma unroll
        for (int i = 0; i < 2; i++) {
            int idx = tid + i * 256;
            int r = idx >> 2, ch = idx & 3;
            cpa16(&AT(bf, r, ch * 4), &g_hs[(size_t)(row0 + r) * H_ + kt + ch * 8]);
            cpa16(&BT(bf, r, ch * 4), &wt[(size_t)(colm + r) * H_ + kt + ch * 8]);
        }
    };

    stage(0, 0);
    CP_COMMIT;

    for (int it = 0; it < H_ / 32; it++) {
        const int bf = it & 1;
        if (it + 1 < H_ / 32) stage((it + 1) * 32, bf ^ 1);
        CP_COMMIT;
        CP_WAIT1;
        __syncthreads();

        #pragma unroll
        for (int kk = 0; kk < 2; kk++) {
            unsigned a[2][4];
            #pragma unroll
            for (int mt = 0; mt < 2; mt++) {
                int r = wm * 32 + mt * 16;
                a[mt][0] = AT(bf, r + g,     kk * 8 + t);
                a[mt][1] = AT(bf, r + g + 8, kk * 8 + t);
                a[mt][2] = AT(bf, r + g,     kk * 8 + t + 4);
                a[mt][3] = AT(bf, r + g + 8, kk * 8 + t + 4);
            }
            #pragma unroll
            for (int nt = 0; nt < 8; nt++) {
                int c = wn * 64 + nt * 8 + g;
                unsigned bb[2] = { BT(bf, c, kk * 8 + t),
                                   BT(bf, c, kk * 8 + t + 4) };
                mma16(acc[0][nt], a[0], bb);
                mma16(acc[1][nt], a[1], bb);
            }
        }
        __syncthreads();
    }

    // Epilogue: +bias+emb, (Q: *log2e/8), f16, scatter.
    #pragma unroll
    for (int nt = 0; nt < 8; nt++) {
        const int cm   = colm + wn * 64 + nt * 8 + 2 * t;
        const float b0 = bias[cm]     + emb[cm];
        const float b1 = bias[cm + 1] + emb[cm + 1];
        const int head = cm >> 6;
        const int d    = cm & 63;
        #pragma unroll
        for (int mt = 0; mt < 2; mt++) {
            int row = row0 + wm * 32 + mt * 16 + g;
            int bt  = row >> 11;
            int s   = row & 2047;
            int bh  = bt * NH_ + head;
            float x0 = (acc[mt][nt][0] + b0) * sc;
            float x1 = (acc[mt][nt][1] + b1) * sc;
            float x2 = (acc[mt][nt][2] + b0) * sc;
            float x3 = (acc[mt][nt][3] + b1) * sc;
            if (sel < 2) {
                __half* dst = (sel ? g_kh : g_qh)
                            + ((size_t)bh * S_ + s) * HD_ + d;
                *(unsigned*)dst             = h2u(x0, x1);
                *(unsigned*)(dst + 8 * HD_) = h2u(x2, x3);
            } else {
                __half* dst = g_vt + (size_t)bh * HD_ * S_;
                dst[(size_t)d       * S_ + s]     = __float2half(x0);
                dst[(size_t)(d + 1) * S_ + s]     = __float2half(x1);
                dst[(size_t)d       * S_ + s + 8] = __float2half(x2);
                dst[(size_t)(d + 1) * S_ + s + 8] = __float2half(x3);
            }
        }
    }
#undef AT
#undef BT
}

// ---------------------------------------------------------------------------
// Kernel 2: flash attention. 8 warps x 16 q-rows, 64-key tiles.
//   3-stage cp.async ring, ONE __syncthreads per tile. exp2-domain softmax
//   with f16x2 EX2 producing packed P fragments directly. Row sums computed
//   by the tensor core via a ones-row appended to V^T (rows 64..71, outside
//   the staged region). Pre-scaled mask.
// ---------------------------------------------------------------------------
#define FS 36
// K [3][64][FS] + V^T [3][72][FS] + mask [3][64]
#define FL_SMEM ((3 * 64 * FS + 3 * 72 * FS + 3 * 64) * 4)

__global__ __launch_bounds__(256, 2) void flash_attn(float* __restrict__ out)
{
    extern __shared__ unsigned fsm[];
    unsigned* KsW = fsm;                  // [3][64 keys][FS]   K: [s][d] f16
    unsigned* VtW = fsm + 3 * 64 * FS;    // [3][72 dims][FS]   V^T + ones/zero rows
    float*    Ms  = (float*)(fsm + 3 * 64 * FS + 3 * 72 * FS);  // [3][64]
#define KT(bf,r,w) KsW[(bf)*64*FS + (r)*FS + (w)]
#define VT(bf,r,w) VtW[(bf)*72*FS + (r)*FS + (w)]

    const int tid  = threadIdx.x;
    const int lane = tid & 31;
    const int wid  = tid >> 5;
    const int g    = lane >> 2;
    const int t    = lane & 3;

    const int bh = blockIdx.y;
    const int b  = bh >> 4, h = bh & 15;
    const __half* Qp  = g_qh + (size_t)bh * S_ * HD_;
    const __half* Kp  = g_kh + (size_t)bh * S_ * HD_;
    const __half* Vtp = g_vt + (size_t)bh * HD_ * S_;
    const float* maskp = g_mask + b * S_;
    const int q0 = blockIdx.x * 128 + wid * 16;

    // Init V^T extension rows once: row 64 = ones (f16 1.0 pairs), 65..71 = 0.
    for (int i = tid; i < 3 * 8 * FS; i += 256) {
        int bf = i / (8 * FS), rem = i % (8 * FS);
        int r = rem / FS, w = rem % FS;
        VT(bf, 64 + r, w) = (r == 0) ? 0x3C003C00u : 0u;
    }

    auto stage = [&](int kt, int bf) {
        #pragma unroll
        for (int i = 0; i < 2; i++) {
            int idx = tid + i * 256;
            int r = idx >> 3, ch = idx & 7;
            cpa16(&KT(bf, r, ch * 4), &Kp[(size_t)(kt + r) * HD_ + ch * 8]);
            cpa16(&VT(bf, r, ch * 4), &Vtp[(size_t)r * S_ + kt + ch * 8]);
        }
        if (tid < 16) cpa16(&Ms[bf * 64 + tid * 4], &maskp[kt + tid * 4]);
    };

    // Q A-fragments (f16 pairs, pre-scaled by log2e/8), resident.
    unsigned qa[4][4];
    {
        const __half* q0p = Qp + (size_t)(q0 + g) * HD_;
        const __half* q8p = q0p + 8 * HD_;
        #pragma unroll
        for (int dc = 0; dc < 4; dc++) {
            qa[dc][0] = *(const unsigned*)(q0p + dc * 16 + 2 * t);
            qa[dc][1] = *(const unsigned*)(q8p + dc * 16 + 2 * t);
            qa[dc][2] = *(const unsigned*)(q0p + dc * 16 + 2 * t + 8);
            qa[dc][3] = *(const unsigned*)(q8p + dc * 16 + 2 * t + 8);
        }
    }

    // o[0..7] = ctx accumulators; o[8] = P@ones row-sum accumulator (lr).
    float o[9][4] = {};
    float mr0 = -1e30f, mr1 = -1e30f;

    // Ring prologue: stages 0 and 1 in flight.
    stage(0, 0);
    CP_COMMIT;
    stage(64, 1);
    CP_COMMIT;

    int bf = 0, bs = 2;   // compute buffer, next stage buffer
    for (int it = 0; it < S_ / 64; it++) {
        CP_WAIT1;          // group 'it' complete (one group may stay in flight)
        __syncthreads();   // single barrier per tile (also orders the row init)

        // S = Q @ K^T  (log2 domain)
        float s[8][4] = {};
        #pragma unroll
        for (int dc = 0; dc < 4; dc++) {
            #pragma unroll
            for (int nt = 0; nt < 8; nt++) {
                unsigned bb[2] = { KT(bf, nt * 8 + g, dc * 8 + t),
                                   KT(bf, nt * 8 + g, dc * 8 + t + 4) };
                mma16(s[nt], qa[dc], bb);
            }
        }

        // mask (already log2-scaled) + row max
        float r0 = -1e30f, r1 = -1e30f;
        #pragma unroll
        for (int nt = 0; nt < 8; nt++) {
            float m0 = Ms[bf * 64 + nt * 8 + 2 * t];
            float m1 = Ms[bf * 64 + nt * 8 + 2 * t + 1];
            s[nt][0] += m0; s[nt][1] += m1; s[nt][2] += m0; s[nt][3] += m1;
            r0 = fmaxf(r0, fmaxf(s[nt][0], s[nt][1]));
            r1 = fmaxf(r1, fmaxf(s[nt][2], s[nt][3]));
        }
        r0 = fmaxf(r0, __shfl_xor_sync(0xffffffffu, r0, 1));
        r0 = fmaxf(r0, __shfl_xor_sync(0xffffffffu, r0, 2));
        r1 = fmaxf(r1, __shfl_xor_sync(0xffffffffu, r1, 1));
        r1 = fmaxf(r1, __shfl_xor_sync(0xffffffffu, r1, 2));

        float mn0 = fmaxf(mr0, r0), mn1 = fmaxf(mr1, r1);
        float al0 = exp2f(mr0 - mn0), al1 = exp2f(mr1 - mn1);
        mr0 = mn0; mr1 = mn1;

        // P = exp2(S - m) straight into packed f16 A-fragments.
        unsigned a[4][4];
        #pragma unroll
        for (int kc = 0; kc < 4; kc++) {
            a[kc][0] = ex2h2(s[2*kc][0]   - mn0, s[2*kc][1]   - mn0);
            a[kc][1] = ex2h2(s[2*kc][2]   - mn1, s[2*kc][3]   - mn1);
            a[kc][2] = ex2h2(s[2*kc+1][0] - mn0, s[2*kc+1][1] - mn0);
            a[kc][3] = ex2h2(s[2*kc+1][2] - mn1, s[2*kc+1][3] - mn1);
        }

        // O = O*alpha + P @ [V | ones]; dt=8 accumulates row sums (lr).
        #pragma unroll
        for (int dt = 0; dt < 9; dt++) {
            o[dt][0] *= al0; o[dt][1] *= al0;
            o[dt][2] *= al1; o[dt][3] *= al1;
        }
        #pragma unroll
        for (int kc = 0; kc < 4; kc++) {
            #pragma unroll
            for (int dt = 0; dt < 9; dt++) {
                unsigned bb[2] = { VT(bf, dt * 8 + g, kc * 8 + t),
                                   VT(bf, dt * 8 + g, kc * 8 + t + 4) };
                mma16(o[dt], a[kc], bb);
            }
        }

        // Stage tile it+2 into ring slot bs.
        if (it + 2 < S_ / 64) stage((it + 2) * 64, bs);
        CP_COMMIT;

        bf = bf == 2 ? 0 : bf + 1;
        bs = bs == 2 ? 0 : bs + 1;
    }

    // Row sums live in column 64 -> t==0 lanes; broadcast within each group.
    float lr0 = __shfl_sync(0xffffffffu, o[8][0], lane & 28);
    float lr1 = __shfl_sync(0xffffffffu, o[8][2], lane & 28);

    // Normalize and write ctx [B, S, NH*HD] f32.
    const float i0 = 1.0f / lr0, i1 = 1.0f / lr1;
    #pragma unroll
    for (int dt = 0; dt < 8; dt++) {
        size_t base = (size_t)(b * S_ + q0 + g) * H_ + h * HD_ + dt * 8 + 2 * t;
        *(float2*)&out[base] = make_float2(o[dt][0] * i0, o[dt][1] * i0);
        *(float2*)&out[base + 8 * (size_t)H_] =
            make_float2(o[dt][2] * i1, o[dt][3] * i1);
    }
#undef KT
#undef VT
}

// ---------------------------------------------------------------------------
extern "C" void kernel_launch(void* const* d_in, const int* in_sizes, int n_in,
                              void* d_out, int out_size)
{
    const float* hs   = (const float*)d_in[0];
    const float* mask = (const float*)d_in[1];
    const float* Wq   = (const float*)d_in[2];
    const float* bq   = (const float*)d_in[3];
    const float* Wk   = (const float*)d_in[4];
    const float* bk   = (const float*)d_in[5];
    const float* Wv   = (const float*)d_in[6];
    const float* bv   = (const float*)d_in[7];
    const float* qe   = (const float*)d_in[8];
    const float* ke   = (const float*)d_in[9];
    const float* ve   = (const float*)d_in[10];
    const int*   idx  = (const int*)d_in[11];

    cudaFuncSetAttribute(qkv_proj, cudaFuncAttributeMaxDynamicSharedMemorySize,
                         QKV_SMEM);
    cudaFuncSetAttribute(flash_attn, cudaFuncAttributeMaxDynamicSharedMemorySize,
                         FL_SMEM);

    cvt_hs<<<8192, 256>>>(hs);
    cvt_mask<<<B_ * S_ / 256, 256>>>(mask);
    cvt_wt<<<dim3(32, 32, 3), dim3(32, 8)>>>(Wq, Wk, Wv);

    dim3 g1(24, 64);
    qkv_proj<<<g1, 256, QKV_SMEM>>>(bq, bk, bv, qe, ke, ve, idx);

    dim3 g2(S_ / 128, B_ * NH_);
    flash_attn<<<g2, 256, FL_SMEM>>>((float*)d_out);
}

// round 17
// speedup vs baseline: 1.1764x; 1.0593x over previous
#include <cuda_runtime.h>
#include <cuda_fp16.h>
#include <cstdint>
#include <math.h>

#define B_  4
#define S_  2048
#define H_  1024
#define NH_ 16
#define HD_ 64
#define L2E 1.44269504088896f

// f16 scratch.
__device__ __half g_hs[8192 * 1024];          // hidden, f16 [8192][1024]
__device__ __half g_wt[3][1024 * 1024];       // W^T f16 [n][k] for Q,K,V
__device__ __half g_qh[64 * 2048 * 64];       // Q f16 [bh][s][d], scaled log2e/8
__device__ __half g_kh[64 * 2048 * 64];       // K f16 [bh][s][d]
__device__ __half g_vt[64 * 64 * 2048];       // V^T f16 [bh][d][s]
__device__ float  g_mask[B_ * S_];            // mask * log2e

__device__ __forceinline__ void mma16(float* c, const unsigned* a, const unsigned* b) {
    asm volatile(
        "mma.sync.aligned.m16n8k16.row.col.f32.f16.f16.f32 "
        "{%0,%1,%2,%3}, {%4,%5,%6,%7}, {%8,%9}, {%0,%1,%2,%3};\n"
        : "+f"(c[0]), "+f"(c[1]), "+f"(c[2]), "+f"(c[3])
        : "r"(a[0]), "r"(a[1]), "r"(a[2]), "r"(a[3]), "r"(b[0]), "r"(b[1]));
}

__device__ __forceinline__ void cpa16(void* dst, const void* src) {
    unsigned d = (unsigned)__cvta_generic_to_shared(dst);
    asm volatile("cp.async.cg.shared.global [%0], [%1], 16;\n" :: "r"(d), "l"(src));
}
#define CP_COMMIT asm volatile("cp.async.commit_group;\n" ::: "memory")
#define CP_WAIT1  asm volatile("cp.async.wait_group 1;\n" ::: "memory")

__device__ __forceinline__ unsigned h2u(float x, float y) {
    __half2 h = __floats2half2_rn(x, y);
    return *reinterpret_cast<unsigned*>(&h);
}

// exp2 of two f32 values, result packed f16x2 {lo=2^x, hi=2^y}.
__device__ __forceinline__ unsigned ex2h2(float x, float y) {
    unsigned h;
    asm("{\n\t.reg .b32 t;\n\t"
        "cvt.rn.f16x2.f32 t, %2, %1;\n\t"   // hi=y, lo=x
        "ex2.approx.f16x2 %0, t;\n\t}"
        : "=r"(h) : "f"(x), "f"(y));
    return h;
}

// ---------------------------------------------------------------------------
// Prep 1: hidden f32 -> f16.
// ---------------------------------------------------------------------------
__global__ __launch_bounds__(256) void cvt_hs(const float* __restrict__ hs) {
    int i = blockIdx.x * 256 + threadIdx.x;
    float4 v = ((const float4*)hs)[i];
    ((uint2*)g_hs)[i] = make_uint2(h2u(v.x, v.y), h2u(v.z, v.w));
}

// ---------------------------------------------------------------------------
// Prep 1b: mask * log2e.
// ---------------------------------------------------------------------------
__global__ __launch_bounds__(256) void cvt_mask(const float* __restrict__ m) {
    int i = blockIdx.x * 256 + threadIdx.x;
    g_mask[i] = m[i] * L2E;
}

// ---------------------------------------------------------------------------
// Prep 2: W -> W^T f16 (tiled transpose). grid (32,32,3), block (32,8).
// ---------------------------------------------------------------------------
__global__ __launch_bounds__(256) void cvt_wt(
    const float* __restrict__ Wq, const float* __restrict__ Wk,
    const float* __restrict__ Wv)
{
    __shared__ float t[32][33];
    const float* W = blockIdx.z == 0 ? Wq : (blockIdx.z == 1 ? Wk : Wv);
    __half* wt = g_wt[blockIdx.z];
    int tx = threadIdx.x, ty = threadIdx.y;
    int n0 = blockIdx.x * 32, k0 = blockIdx.y * 32;
    #pragma unroll
    for (int j = 0; j < 4; j++)
        t[ty + 8 * j][tx] = W[(size_t)(k0 + ty + 8 * j) * H_ + n0 + tx];
    __syncthreads();
    #pragma unroll
    for (int j = 0; j < 4; j++)
        wt[(size_t)(n0 + ty + 8 * j) * H_ + k0 + tx] =
            __float2half(t[tx][ty + 8 * j]);
}

// ---------------------------------------------------------------------------
// Kernel 1: fused QKV projection, f16 mma m16n8k16.
//   BM=128, BN=128, BK=32. 8 warps (4m x 2n), warp tile 32x64.
//   3-stage cp.async ring, ONE __syncthreads per iteration, staging issued
//   after compute (same skew-safety argument as flash_attn's ring).
// ---------------------------------------------------------------------------
#define TS 20   // tile row stride in 32-bit words (16 data + 4 pad)
#define QST2 (2 * 128 * TS)              // words per stage (A tile + B tile)
#define QKV_SMEM (3 * QST2 * 4)

__global__ __launch_bounds__(256, 2) void qkv_proj(
    const float* __restrict__ bq, const float* __restrict__ bk,
    const float* __restrict__ bv,
    const float* __restrict__ qe, const float* __restrict__ ke,
    const float* __restrict__ ve,
    const int* __restrict__ indexp)
{
    extern __shared__ unsigned qsm[];
#define AT(bf,r,w) qsm[(bf)*QST2 + (r)*TS + (w)]
#define BT(bf,r,w) qsm[(bf)*QST2 + 128*TS + (r)*TS + (w)]

    const int tid  = threadIdx.x;
    const int lane = tid & 31;
    const int wid  = tid >> 5;
    const int g    = lane >> 2;
    const int t    = lane & 3;
    const int wm   = wid & 3;
    const int wn   = wid >> 2;

    const int nb  = blockIdx.x;   // 0..23, 8 per matrix
    const int mb  = blockIdx.y;   // 0..63
    const int sel = nb >> 3;      // 0=Q, 1=K, 2=V

    const __half* wt  = g_wt[sel];
    const float* bias = sel == 0 ? bq : (sel == 1 ? bk : bv);
    const float* emb  = (sel == 0 ? qe : (sel == 1 ? ke : ve)) + indexp[0] * H_;
    const float sc    = sel == 0 ? (0.125f * L2E) : 1.0f;

    const int colm = (nb & 7) * 128;
    const int row0 = mb * 128;

    float acc[2][8][4] = {};

    auto stage = [&](int kt, int bf) {
        #pragma unroll
        for (int i = 0; i < 2; i++) {
            int idx = tid + i * 256;
            int r = idx >> 2, ch = idx & 3;
            cpa16(&AT(bf, r, ch * 4), &g_hs[(size_t)(row0 + r) * H_ + kt + ch * 8]);
            cpa16(&BT(bf, r, ch * 4), &wt[(size_t)(colm + r) * H_ + kt + ch * 8]);
        }
    };

    // Ring prologue: chunks 0 and 1 in flight.
    stage(0, 0);
    CP_COMMIT;
    stage(32, 1);
    CP_COMMIT;

    int bf = 0, bs = 2;   // compute buffer, next stage buffer
    for (int it = 0; it < H_ / 32; it++) {
        CP_WAIT1;          // chunk 'it' staged (one newer group may stay in flight)
        __syncthreads();   // single barrier per iteration

        #pragma unroll
        for (int kk = 0; kk < 2; kk++) {
            unsigned a[2][4];
            #pragma unroll
            for (int mt = 0; mt < 2; mt++) {
                int r = wm * 32 + mt * 16;
                a[mt][0] = AT(bf, r + g,     kk * 8 + t);
                a[mt][1] = AT(bf, r + g + 8, kk * 8 + t);
                a[mt][2] = AT(bf, r + g,     kk * 8 + t + 4);
                a[mt][3] = AT(bf, r + g + 8, kk * 8 + t + 4);
            }
            #pragma unroll
            for (int nt = 0; nt < 8; nt++) {
                int c = wn * 64 + nt * 8 + g;
                unsigned bb[2] = { BT(bf, c, kk * 8 + t),
                                   BT(bf, c, kk * 8 + t + 4) };
                mma16(acc[0][nt], a[0], bb);
                mma16(acc[1][nt], a[1], bb);
            }
        }

        // Stage chunk it+2 into ring slot bs (its old readers finished at
        // iteration it-1; the barrier above proves all warps are past that).
        if (it + 2 < H_ / 32) stage((it + 2) * 32, bs);
        CP_COMMIT;   // unconditional: keeps wait_group accounting uniform

        bf = bf == 2 ? 0 : bf + 1;
        bs = bs == 2 ? 0 : bs + 1;
    }

    // Epilogue: +bias+emb, (Q: *log2e/8), f16, scatter.
    #pragma unroll
    for (int nt = 0; nt < 8; nt++) {
        const int cm   = colm + wn * 64 + nt * 8 + 2 * t;
        const float b0 = bias[cm]     + emb[cm];
        const float b1 = bias[cm + 1] + emb[cm + 1];
        const int head = cm >> 6;
        const int d    = cm & 63;
        #pragma unroll
        for (int mt = 0; mt < 2; mt++) {
            int row = row0 + wm * 32 + mt * 16 + g;
            int bt  = row >> 11;
            int s   = row & 2047;
            int bh  = bt * NH_ + head;
            float x0 = (acc[mt][nt][0] + b0) * sc;
            float x1 = (acc[mt][nt][1] + b1) * sc;
            float x2 = (acc[mt][nt][2] + b0) * sc;
            float x3 = (acc[mt][nt][3] + b1) * sc;
            if (sel < 2) {
                __half* dst = (sel ? g_kh : g_qh)
                            + ((size_t)bh * S_ + s) * HD_ + d;
                *(unsigned*)dst             = h2u(x0, x1);
                *(unsigned*)(dst + 8 * HD_) = h2u(x2, x3);
            } else {
                __half* dst = g_vt + (size_t)bh * HD_ * S_;
                dst[(size_t)d       * S_ + s]     = __float2half(x0);
                dst[(size_t)(d + 1) * S_ + s]     = __float2half(x1);
                dst[(size_t)d       * S_ + s + 8] = __float2half(x2);
                dst[(size_t)(d + 1) * S_ + s + 8] = __float2half(x3);
            }
        }
    }
#undef AT
#undef BT
}

// ---------------------------------------------------------------------------
// Kernel 2: flash attention (round-16 proven version).
//   8 warps x 16 q-rows, 64-key tiles. 3-stage cp.async ring, ONE
//   __syncthreads per tile. f16x2 EX2 softmax -> packed P fragments.
//   Row sums via ones-row in V^T. Pre-scaled mask.
// ---------------------------------------------------------------------------
#define FS 36
// K [3][64][FS] + V^T [3][72][FS] + mask [3][64]
#define FL_SMEM ((3 * 64 * FS + 3 * 72 * FS + 3 * 64) * 4)

__global__ __launch_bounds__(256, 2) void flash_attn(float* __restrict__ out)
{
    extern __shared__ unsigned fsm[];
    unsigned* KsW = fsm;                  // [3][64 keys][FS]   K: [s][d] f16
    unsigned* VtW = fsm + 3 * 64 * FS;    // [3][72 dims][FS]   V^T + ones/zero rows
    float*    Ms  = (float*)(fsm + 3 * 64 * FS + 3 * 72 * FS);  // [3][64]
#define KT(bf,r,w) KsW[(bf)*64*FS + (r)*FS + (w)]
#define VT(bf,r,w) VtW[(bf)*72*FS + (r)*FS + (w)]

    const int tid  = threadIdx.x;
    const int lane = tid & 31;
    const int wid  = tid >> 5;
    const int g    = lane >> 2;
    const int t    = lane & 3;

    const int bh = blockIdx.y;
    const int b  = bh >> 4, h = bh & 15;
    const __half* Qp  = g_qh + (size_t)bh * S_ * HD_;
    const __half* Kp  = g_kh + (size_t)bh * S_ * HD_;
    const __half* Vtp = g_vt + (size_t)bh * HD_ * S_;
    const float* maskp = g_mask + b * S_;
    const int q0 = blockIdx.x * 128 + wid * 16;

    // Init V^T extension rows once: row 64 = ones (f16 1.0 pairs), 65..71 = 0.
    for (int i = tid; i < 3 * 8 * FS; i += 256) {
        int bf = i / (8 * FS), rem = i % (8 * FS);
        int r = rem / FS, w = rem % FS;
        VT(bf, 64 + r, w) = (r == 0) ? 0x3C003C00u : 0u;
    }

    auto stage = [&](int kt, int bf) {
        #pragma unroll
        for (int i = 0; i < 2; i++) {
            int idx = tid + i * 256;
            int r = idx >> 3, ch = idx & 7;
            cpa16(&KT(bf, r, ch * 4), &Kp[(size_t)(kt + r) * HD_ + ch * 8]);
            cpa16(&VT(bf, r, ch * 4), &Vtp[(size_t)r * S_ + kt + ch * 8]);
        }
        if (tid < 16) cpa16(&Ms[bf * 64 + tid * 4], &maskp[kt + tid * 4]);
    };

    // Q A-fragments (f16 pairs, pre-scaled by log2e/8), resident.
    unsigned qa[4][4];
    {
        const __half* q0p = Qp + (size_t)(q0 + g) * HD_;
        const __half* q8p = q0p + 8 * HD_;
        #pragma unroll
        for (int dc = 0; dc < 4; dc++) {
            qa[dc][0] = *(const unsigned*)(q0p + dc * 16 + 2 * t);
            qa[dc][1] = *(const unsigned*)(q8p + dc * 16 + 2 * t);
            qa[dc][2] = *(const unsigned*)(q0p + dc * 16 + 2 * t + 8);
            qa[dc][3] = *(const unsigned*)(q8p + dc * 16 + 2 * t + 8);
        }
    }

    // o[0..7] = ctx accumulators; o[8] = P@ones row-sum accumulator (lr).
    float o[9][4] = {};
    float mr0 = -1e30f, mr1 = -1e30f;

    // Ring prologue: stages 0 and 1 in flight.
    stage(0, 0);
    CP_COMMIT;
    stage(64, 1);
    CP_COMMIT;

    int bf = 0, bs = 2;   // compute buffer, next stage buffer
    for (int it = 0; it < S_ / 64; it++) {
        CP_WAIT1;          // group 'it' complete (one group may stay in flight)
        __syncthreads();   // single barrier per tile (also orders the row init)

        // S = Q @ K^T  (log2 domain)
        float s[8][4] = {};
        #pragma unroll
        for (int dc = 0; dc < 4; dc++) {
            #pragma unroll
            for (int nt = 0; nt < 8; nt++) {
                unsigned bb[2] = { KT(bf, nt * 8 + g, dc * 8 + t),
                                   KT(bf, nt * 8 + g, dc * 8 + t + 4) };
                mma16(s[nt], qa[dc], bb);
            }
        }

        // mask (already log2-scaled) + row max
        float r0 = -1e30f, r1 = -1e30f;
        #pragma unroll
        for (int nt = 0; nt < 8; nt++) {
            float m0 = Ms[bf * 64 + nt * 8 + 2 * t];
            float m1 = Ms[bf * 64 + nt * 8 + 2 * t + 1];
            s[nt][0] += m0; s[nt][1] += m1; s[nt][2] += m0; s[nt][3] += m1;
            r0 = fmaxf(r0, fmaxf(s[nt][0], s[nt][1]));
            r1 = fmaxf(r1, fmaxf(s[nt][2], s[nt][3]));
        }
        r0 = fmaxf(r0, __shfl_xor_sync(0xffffffffu, r0, 1));
        r0 = fmaxf(r0, __shfl_xor_sync(0xffffffffu, r0, 2));
        r1 = fmaxf(r1, __shfl_xor_sync(0xffffffffu, r1, 1));
        r1 = fmaxf(r1, __shfl_xor_sync(0xffffffffu, r1, 2));

        float mn0 = fmaxf(mr0, r0), mn1 = fmaxf(mr1, r1);
        float al0 = exp2f(mr0 - mn0), al1 = exp2f(mr1 - mn1);
        mr0 = mn0; mr1 = mn1;

        // P = exp2(S - m) straight into packed f16 A-fragments.
        unsigned a[4][4];
        #pragma unroll
        for (int kc = 0; kc < 4; kc++) {
            a[kc][0] = ex2h2(s[2*kc][0]   - mn0, s[2*kc][1]   - mn0);
            a[kc][1] = ex2h2(s[2*kc][2]   - mn1, s[2*kc][3]   - mn1);
            a[kc][2] = ex2h2(s[2*kc+1][0] - mn0, s[2*kc+1][1] - mn0);
            a[kc][3] = ex2h2(s[2*kc+1][2] - mn1, s[2*kc+1][3] - mn1);
        }

        // O = O*alpha + P @ [V | ones]; dt=8 accumulates row sums (lr).
        #pragma unroll
        for (int dt = 0; dt < 9; dt++) {
            o[dt][0] *= al0; o[dt][1] *= al0;
            o[dt][2] *= al1; o[dt][3] *= al1;
        }
        #pragma unroll
        for (int kc = 0; kc < 4; kc++) {
            #pragma unroll
            for (int dt = 0; dt < 9; dt++) {
                unsigned bb[2] = { VT(bf, dt * 8 + g, kc * 8 + t),
                                   VT(bf, dt * 8 + g, kc * 8 + t + 4) };
                mma16(o[dt], a[kc], bb);
            }
        }

        // Stage tile it+2 into ring slot bs.
        if (it + 2 < S_ / 64) stage((it + 2) * 64, bs);
        CP_COMMIT;

        bf = bf == 2 ? 0 : bf + 1;
        bs = bs == 2 ? 0 : bs + 1;
    }

    // Row sums live in column 64 -> t==0 lanes; broadcast within each group.
    float lr0 = __shfl_sync(0xffffffffu, o[8][0], lane & 28);
    float lr1 = __shfl_sync(0xffffffffu, o[8][2], lane & 28);

    // Normalize and write ctx [B, S, NH*HD] f32.
    const float i0 = 1.0f / lr0, i1 = 1.0f / lr1;
    #pragma unroll
    for (int dt = 0; dt < 8; dt++) {
        size_t base = (size_t)(b * S_ + q0 + g) * H_ + h * HD_ + dt * 8 + 2 * t;
        *(float2*)&out[base] = make_float2(o[dt][0] * i0, o[dt][1] * i0);
        *(float2*)&out[base + 8 * (size_t)H_] =
            make_float2(o[dt][2] * i1, o[dt][3] * i1);
    }
#undef KT
#undef VT
}

// ---------------------------------------------------------------------------
extern "C" void kernel_launch(void* const* d_in, const int* in_sizes, int n_in,
                              void* d_out, int out_size)
{
    const float* hs   = (const float*)d_in[0];
    const float* mask = (const float*)d_in[1];
    const float* Wq   = (const float*)d_in[2];
    const float* bq   = (const float*)d_in[3];
    const float* Wk   = (const float*)d_in[4];
    const float* bk   = (const float*)d_in[5];
    const float* Wv   = (const float*)d_in[6];
    const float* bv   = (const float*)d_in[7];
    const float* qe   = (const float*)d_in[8];
    const float* ke   = (const float*)d_in[9];
    const float* ve   = (const float*)d_in[10];
    const int*   idx  = (const int*)d_in[11];

    cudaFuncSetAttribute(qkv_proj, cudaFuncAttributeMaxDynamicSharedMemorySize,
                         QKV_SMEM);
    cudaFuncSetAttribute(flash_attn, cudaFuncAttributeMaxDynamicSharedMemorySize,
                         FL_SMEM);

    cvt_hs<<<8192, 256>>>(hs);
    cvt_mask<<<B_ * S_ / 256, 256>>>(mask);
    cvt_wt<<<dim3(32, 32, 3), dim3(32, 8)>>>(Wq, Wk, Wv);

    dim3 g1(24, 64);
    qkv_proj<<<g1, 256, QKV_SMEM>>>(bq, bk, bv, qe, ke, ve, idx);

    dim3 g2(S_ / 128, B_ * NH_);
    flash_attn<<<g2, 256, FL_SMEM>>>((float*)d_out);
}